// round 15
// baseline (speedup 1.0000x reference)
#include <cuda_runtime.h>
#include <cuda_fp16.h>
#include <math.h>

#define NN 50000
#define EE 1600000
#define GG 256
#define HH 128
#define ED 16

// ---------------- scratch (static device globals; no allocs) ----------------
// blob = [degcnt (NN ints) | ecolsum (ED floats)] — zeroed by ONE memset
__device__ __align__(128) int g_blob[NN + ED];
#define G_DEGCNT  (g_blob)
#define G_ECOLSUM ((float*)(g_blob + NN))

__device__ int    g_rowptr[NN + 1];   // edge-only CSR offsets
__device__ int    g_wp[NN];
__device__ float  g_dis[NN];
__device__ __align__(128) int    g_col[EE];
__device__ __align__(128) __half g_t[NN * HH];   // dis-prescaled GEMM output (fp16)
__device__ __align__(128) float  g_x1[NN * HH];  // ping
__device__ __align__(128) float  g_x2[NN * HH];  // pong
__device__ float  g_meanvec[HH];

// ---------------- degree histogram (scalar — proven form) ----------------
__global__ void degree_kernel(const int* __restrict__ ei) {
    int e = blockIdx.x * blockDim.x + threadIdx.x;
    if (e < EE) atomicAdd(&G_DEGCNT[ei[EE + e]], 1);   // dst = ei[1][e]
}

// ---------------- single-block exclusive scan (edge-only) + dis + wp ----------------
#define SCAN_T 1024
__global__ __launch_bounds__(SCAN_T) void scan_kernel() {
    __shared__ int sh[SCAN_T];
    const int chunk = (NN + SCAN_T - 1) / SCAN_T;
    int t  = threadIdx.x;
    int lo = t * chunk;
    int hi = min(lo + chunk, NN);
    int sum = 0;
    for (int i = lo; i < hi; i++) sum += G_DEGCNT[i];   // edge counts
    sh[t] = sum;
    __syncthreads();
    for (int off = 1; off < SCAN_T; off <<= 1) {
        int v = (t >= off) ? sh[t - off] : 0;
        __syncthreads();
        sh[t] += v;
        __syncthreads();
    }
    int run = sh[t] - sum;
    for (int i = lo; i < hi; i++) {
        int c = G_DEGCNT[i];
        g_rowptr[i] = run;
        g_wp[i]     = run;
        g_dis[i]    = rsqrtf((float)(c + 1));   // + self-loop
        run += c;
    }
    if (t == SCAN_T - 1) g_rowptr[NN] = sh[SCAN_T - 1];
}

// ---------------- CSR fill (scalar — proven form) ----------------
__global__ void csr_fill_edges(const int* __restrict__ ei) {
    int e = blockIdx.x * blockDim.x + threadIdx.x;
    if (e >= EE) return;
    int s = ei[e];
    int d = ei[EE + e];
    int pos = atomicAdd(&g_wp[d], 1);
    g_col[pos] = s;
}

// ---------------- edge_attr column sums: float4, 4 cols/thread ----------------
__global__ __launch_bounds__(256) void edge_colsum_kernel(const float* __restrict__ ea) {
    __shared__ float sh[ED];
    if (threadIdx.x < ED) sh[threadIdx.x] = 0.f;
    __syncthreads();
    const long long total4 = (long long)EE * ED / 4;            // float4 count
    long long idx = (long long)blockIdx.x * blockDim.x + threadIdx.x;
    const long long stride = (long long)gridDim.x * blockDim.x;  // multiple of 4
    int cg = (int)(idx & 3) * 4;                                 // column group, invariant
    float4 s4 = make_float4(0.f, 0.f, 0.f, 0.f);
    for (; idx < total4; idx += stride) {
        float4 v = *(const float4*)(ea + idx * 4);
        s4.x += v.x; s4.y += v.y; s4.z += v.z; s4.w += v.w;
    }
    atomicAdd(&sh[cg + 0], s4.x);
    atomicAdd(&sh[cg + 1], s4.y);
    atomicAdd(&sh[cg + 2], s4.z);
    atomicAdd(&sh[cg + 3], s4.w);
    __syncthreads();
    if (threadIdx.x < ED) atomicAdd(&G_ECOLSUM[threadIdx.x], sh[threadIdx.x]);
}

__global__ void meanvec_kernel(const float* __restrict__ eW, const float* __restrict__ eb) {
    int h = threadIdx.x;
    const float inv = 1.0f / (float)EE;
    float m = eb[h];
    #pragma unroll
    for (int k = 0; k < ED; k++) m += (G_ECOLSUM[k] * inv) * eW[k * HH + h];
    g_meanvec[h] = m;
}

// ---------------- SGEMM 64x128 tile, K-step 8, 256 threads, 4x8 per thread ----------------
// Small M-tile -> 32 acc regs/thread -> 4 CTAs/SM (50% occ) to hide LDS latency.
// epilogue scales by dis[row], stores fp16
__global__ __launch_bounds__(256, 4) void sgemm_kernel(const float* __restrict__ A,
                                                       const float* __restrict__ B,
                                                       __half* __restrict__ C, int M) {
    __shared__ float As[8][64];
    __shared__ float Bs[8][128];
    const int tid  = threadIdx.x;
    const int row0 = blockIdx.x * 64;
    const int ar = tid >> 2, ac = (tid & 3) * 2;     // A tile: 64 rows x 8 k, float2 each
    const int br = tid >> 5, bc = (tid & 31) * 4;    // B tile: 8 k x 128 cols, float4 each
    const int ty = tid >> 4, tx = tid & 15;          // 16 x 16 compute layout
    const int gr = row0 + ar;

    float acc[4][8];
    #pragma unroll
    for (int m = 0; m < 4; m++)
        #pragma unroll
        for (int n = 0; n < 8; n++) acc[m][n] = 0.f;

    for (int k0 = 0; k0 < 128; k0 += 8) {
        float2 av = (gr < M) ? *(const float2*)&A[(size_t)gr * 128 + k0 + ac]
                             : make_float2(0.f, 0.f);
        As[ac + 0][ar] = av.x;
        As[ac + 1][ar] = av.y;
        *(float4*)&Bs[br][bc] = *(const float4*)&B[(size_t)(k0 + br) * 128 + bc];
        __syncthreads();
        #pragma unroll
        for (int k = 0; k < 8; k++) {
            float a[4], b[8];
            #pragma unroll
            for (int m = 0; m < 4; m++) a[m] = As[k][ty * 4 + m];
            #pragma unroll
            for (int n = 0; n < 8; n++) b[n] = Bs[k][tx * 8 + n];
            #pragma unroll
            for (int m = 0; m < 4; m++)
                #pragma unroll
                for (int n = 0; n < 8; n++) acc[m][n] = fmaf(a[m], b[n], acc[m][n]);
        }
        __syncthreads();
    }
    #pragma unroll
    for (int m = 0; m < 4; m++) {
        int row = row0 + ty * 4 + m;
        if (row < M) {
            float s = g_dis[row];
            __align__(16) __half2 h[4];
            #pragma unroll
            for (int q = 0; q < 4; q++)
                h[q] = __floats2half2_rn(acc[m][2 * q] * s, acc[m][2 * q + 1] * s);
            *(uint4*)&C[(size_t)row * 128 + tx * 8] = *(const uint4*)h;
        }
    }
}

// ---------------- aggregation: warp/node, fp16 gather (R4-proven form) ----------------
__global__ __launch_bounds__(256) void agg_kernel(const __half* __restrict__ t,
                                                  const float* __restrict__ bias,
                                                  float* __restrict__ out,
                                                  int addmean) {
    int warp = (blockIdx.x * blockDim.x + threadIdx.x) >> 5;
    int lane = threadIdx.x & 31;
    if (warp >= NN) return;
    int s = g_rowptr[warp];
    int e = g_rowptr[warp + 1];

    // self-loop: t' row of this node (weight 1; dis^2 comes from prescale + postscale)
    uint2 raw = *(const uint2*)(t + (size_t)warp * 128 + lane * 4);
    float2 p0 = __half22float2(*(const __half2*)&raw.x);
    float2 p1 = __half22float2(*(const __half2*)&raw.y);
    float4 acc  = make_float4(p0.x, p0.y, p1.x, p1.y);
    float4 acc2 = make_float4(0.f, 0.f, 0.f, 0.f);

    int p = s;
    for (; p + 1 < e; p += 2) {
        int c0 = g_col[p];
        int c1 = g_col[p + 1];
        uint2 r0 = *(const uint2*)(t + (size_t)c0 * 128 + lane * 4);
        uint2 r1 = *(const uint2*)(t + (size_t)c1 * 128 + lane * 4);
        float2 a0 = __half22float2(*(const __half2*)&r0.x);
        float2 a1 = __half22float2(*(const __half2*)&r0.y);
        float2 b0 = __half22float2(*(const __half2*)&r1.x);
        float2 b1 = __half22float2(*(const __half2*)&r1.y);
        acc.x  += a0.x; acc.y  += a0.y; acc.z  += a1.x; acc.w  += a1.y;
        acc2.x += b0.x; acc2.y += b0.y; acc2.z += b1.x; acc2.w += b1.y;
    }
    if (p < e) {
        int c0 = g_col[p];
        uint2 r0 = *(const uint2*)(t + (size_t)c0 * 128 + lane * 4);
        float2 a0 = __half22float2(*(const __half2*)&r0.x);
        float2 a1 = __half22float2(*(const __half2*)&r0.y);
        acc.x += a0.x; acc.y += a0.y; acc.z += a1.x; acc.w += a1.y;
    }
    acc.x += acc2.x; acc.y += acc2.y; acc.z += acc2.z; acc.w += acc2.w;

    float disd = g_dis[warp];
    float4 bb = *(const float4*)(bias + lane * 4);
    acc.x = fmaxf(fmaf(acc.x, disd, bb.x), 0.f);
    acc.y = fmaxf(fmaf(acc.y, disd, bb.y), 0.f);
    acc.z = fmaxf(fmaf(acc.z, disd, bb.z), 0.f);
    acc.w = fmaxf(fmaf(acc.w, disd, bb.w), 0.f);
    if (addmean) {
        float4 mv = *(const float4*)(g_meanvec + lane * 4);
        acc.x += mv.x; acc.y += mv.y; acc.z += mv.z; acc.w += mv.w;
    }
    *(float4*)(out + (size_t)warp * 128 + lane * 4) = acc;
}

// ---------------- fused pooling (max+mean per graph) + MLP ----------------
__global__ __launch_bounds__(128) void pool_mlp_kernel(const float* __restrict__ x,
                                                       const int* __restrict__ batch,
                                                       const float* __restrict__ l1W,
                                                       const float* __restrict__ l1b,
                                                       const float* __restrict__ l2W,
                                                       const float* __restrict__ l2b,
                                                       float* __restrict__ out) {
    int g = blockIdx.x;
    int d = threadIdx.x;   // 0..127
    int lo = 0, hi = NN;
    while (lo < hi) { int mid = (lo + hi) >> 1; if (batch[mid] < g) lo = mid + 1; else hi = mid; }
    int start = lo;
    hi = NN;
    while (lo < hi) { int mid = (lo + hi) >> 1; if (batch[mid] < g + 1) lo = mid + 1; else hi = mid; }
    int end = lo;

    float mx = -3.402823466e38f, sm = 0.f;
    for (int i = start; i < end; i++) {
        float v = x[(size_t)i * 128 + d];
        mx = fmaxf(mx, v);
        sm += v;
    }
    __shared__ float pooled[256];
    __shared__ float hid[64];
    pooled[d]       = mx;
    pooled[128 + d] = sm / (float)(end - start);
    __syncthreads();
    if (d < 64) {
        float h = l1b[d];
        #pragma unroll 8
        for (int k = 0; k < 256; k++) h = fmaf(pooled[k], l1W[k * 64 + d], h);
        hid[d] = fmaxf(h, 0.f);
    }
    __syncthreads();
    if (d == 0) {
        float s = l2b[0];
        #pragma unroll 8
        for (int k = 0; k < 64; k++) s = fmaf(hid[k], l2W[k], s);
        out[g] = s;
    }
}

// ---------------- launch ----------------
extern "C" void kernel_launch(void* const* d_in, const int* in_sizes, int n_in,
                              void* d_out, int out_size) {
    const float* x    = (const float*)d_in[0];
    const int*   ei   = (const int*)  d_in[1];
    const float* ea   = (const float*)d_in[2];
    const int*   bat  = (const int*)  d_in[3];
    const float* W0   = (const float*)d_in[4];
    const float* b0   = (const float*)d_in[5];
    const float* W1   = (const float*)d_in[6];
    const float* b1   = (const float*)d_in[7];
    const float* W2   = (const float*)d_in[8];
    const float* b2   = (const float*)d_in[9];
    const float* eW   = (const float*)d_in[10];
    const float* eb   = (const float*)d_in[11];
    const float* l1W  = (const float*)d_in[12];
    const float* l1b  = (const float*)d_in[13];
    const float* l2W  = (const float*)d_in[14];
    const float* l2b  = (const float*)d_in[15];
    float* out = (float*)d_out;

    __half *t;
    float *x1, *x2;
    int *blob;
    cudaGetSymbolAddress((void**)&t,  g_t);
    cudaGetSymbolAddress((void**)&x1, g_x1);
    cudaGetSymbolAddress((void**)&x2, g_x2);
    cudaGetSymbolAddress((void**)&blob, g_blob);

    const int TB = 256;
    const int gemm_grid = (NN + 63) / 64;
    const int agg_grid  = (NN * 32 + TB - 1) / TB;

    cudaMemsetAsync(blob, 0, (NN + ED) * sizeof(int));
    degree_kernel<<<(EE + TB - 1) / TB, TB>>>(ei);
    scan_kernel<<<1, SCAN_T>>>();
    csr_fill_edges<<<(EE + TB - 1) / TB, TB>>>(ei);
    sgemm_kernel<<<gemm_grid, TB>>>(x, W0, t, NN);
    agg_kernel<<<agg_grid, TB>>>(t, b0, x1, 0);
    edge_colsum_kernel<<<1024, TB>>>(ea);
    meanvec_kernel<<<1, HH>>>(eW, eb);
    sgemm_kernel<<<gemm_grid, TB>>>(x1, W1, t, NN);
    agg_kernel<<<agg_grid, TB>>>(t, b1, x2, 0);
    sgemm_kernel<<<gemm_grid, TB>>>(x2, W2, t, NN);
    agg_kernel<<<agg_grid, TB>>>(t, b2, x1, 1);
    pool_mlp_kernel<<<GG, HH>>>(x1, bat, l1W, l1b, l2W, l2b, out);
}

// round 17
// speedup vs baseline: 1.1074x; 1.1074x over previous
#include <cuda_runtime.h>
#include <cuda_fp16.h>
#include <math.h>

#define NN 50000
#define EE 1600000
#define GG 256
#define HH 128
#define ED 16

#define GEMM_GRID ((NN + 127) / 128)        // 391
#define DEG_GRID  ((EE + 255) / 256)        // 6250
#define COL_GRID  1024

// ---------------- scratch (static device globals; no allocs) ----------------
// blob = [degcnt (NN ints) | ecolsum (ED floats)] — zeroed by ONE memset
__device__ __align__(128) int g_blob[NN + ED];
#define G_DEGCNT  (g_blob)
#define G_ECOLSUM ((float*)(g_blob + NN))

__device__ int    g_rowptr[NN + 1];
__device__ int    g_wp[NN];
__device__ float  g_dis[NN];
__device__ __align__(128) int    g_col[EE];
__device__ __align__(128) __half g_t[NN * HH];   // dis-prescaled GEMM output (fp16)
__device__ __align__(128) float  g_x1[NN * HH];
__device__ __align__(128) float  g_x2[NN * HH];
__device__ float  g_meanvec[HH];

// ---------------- FUSED: gemm0 + degree histogram + edge_attr colsum ----------------
// blockIdx [0, GEMM_GRID)                       : sgemm tile (R4-proven body)
// blockIdx [GEMM_GRID, GEMM_GRID+DEG_GRID)      : degree histogram (scalar, proven)
// blockIdx [GEMM_GRID+DEG_GRID, +COL_GRID)      : float4 colsum (R13-proven)
__global__ __launch_bounds__(256) void fused0_kernel(const float* __restrict__ A,
                                                     const float* __restrict__ B,
                                                     __half* __restrict__ C,
                                                     const int* __restrict__ ei,
                                                     const float* __restrict__ ea,
                                                     int M) {
    const int tid = threadIdx.x;
    if (blockIdx.x < GEMM_GRID) {
        // ---- sgemm 128x128 tile, K-step 8 ----
        __shared__ float As[8][128];
        __shared__ float Bs[8][128];
        const int row0 = blockIdx.x * 128;
        const int ar = tid >> 1, ac = (tid & 1) * 4;
        const int br = tid >> 5, bc = (tid & 31) * 4;
        const int ty = tid >> 4, tx = tid & 15;

        float acc[8][8];
        #pragma unroll
        for (int m = 0; m < 8; m++)
            #pragma unroll
            for (int n = 0; n < 8; n++) acc[m][n] = 0.f;

        for (int k0 = 0; k0 < 128; k0 += 8) {
            int gr = row0 + ar;
            float4 av = (gr < M) ? *(const float4*)&A[(size_t)gr * 128 + k0 + ac]
                                 : make_float4(0.f, 0.f, 0.f, 0.f);
            As[ac + 0][ar] = av.x;
            As[ac + 1][ar] = av.y;
            As[ac + 2][ar] = av.z;
            As[ac + 3][ar] = av.w;
            *(float4*)&Bs[br][bc] = *(const float4*)&B[(size_t)(k0 + br) * 128 + bc];
            __syncthreads();
            #pragma unroll
            for (int k = 0; k < 8; k++) {
                float a[8], b[8];
                #pragma unroll
                for (int m = 0; m < 8; m++) a[m] = As[k][ty * 8 + m];
                #pragma unroll
                for (int n = 0; n < 8; n++) b[n] = Bs[k][tx * 8 + n];
                #pragma unroll
                for (int m = 0; m < 8; m++)
                    #pragma unroll
                    for (int n = 0; n < 8; n++) acc[m][n] = fmaf(a[m], b[n], acc[m][n]);
            }
            __syncthreads();
        }
        #pragma unroll
        for (int m = 0; m < 8; m++) {
            int row = row0 + ty * 8 + m;
            if (row < M) {
                // NOTE: x-prescale uses dis computed LAST call? No — layer-0 fused
                // gemm runs BEFORE scan this launch, so epilogue must NOT scale here.
                // Scaling by dis[row] is deferred to agg (see agg_kernel presc arg).
                __align__(16) __half2 h[4];
                #pragma unroll
                for (int q = 0; q < 4; q++)
                    h[q] = __floats2half2_rn(acc[m][2 * q], acc[m][2 * q + 1]);
                *(uint4*)&C[(size_t)row * 128 + tx * 8] = *(const uint4*)h;
            }
        }
    } else if (blockIdx.x < GEMM_GRID + DEG_GRID) {
        // ---- degree histogram ----
        int e = (blockIdx.x - GEMM_GRID) * 256 + tid;
        if (e < EE) atomicAdd(&G_DEGCNT[ei[EE + e]], 1);
    } else {
        // ---- edge_attr colsum, float4 ----
        __shared__ float sh[ED];
        if (tid < ED) sh[tid] = 0.f;
        __syncthreads();
        const long long total4 = (long long)EE * ED / 4;
        long long idx = (long long)(blockIdx.x - GEMM_GRID - DEG_GRID) * 256 + tid;
        const long long stride = (long long)COL_GRID * 256;
        int cg = (int)(idx & 3) * 4;
        float4 s4 = make_float4(0.f, 0.f, 0.f, 0.f);
        for (; idx < total4; idx += stride) {
            float4 v = *(const float4*)(ea + idx * 4);
            s4.x += v.x; s4.y += v.y; s4.z += v.z; s4.w += v.w;
        }
        atomicAdd(&sh[cg + 0], s4.x);
        atomicAdd(&sh[cg + 1], s4.y);
        atomicAdd(&sh[cg + 2], s4.z);
        atomicAdd(&sh[cg + 3], s4.w);
        __syncthreads();
        if (tid < ED) atomicAdd(&G_ECOLSUM[tid], sh[tid]);
    }
}

// ---------------- scan (block 0) + meanvec (block 1) ----------------
#define SCAN_T 1024
__global__ __launch_bounds__(SCAN_T) void scan_meanvec_kernel(const float* __restrict__ eW,
                                                              const float* __restrict__ eb) {
    if (blockIdx.x == 1) {
        int h = threadIdx.x;
        if (h < HH) {
            const float inv = 1.0f / (float)EE;
            float m = eb[h];
            #pragma unroll
            for (int k = 0; k < ED; k++) m += (G_ECOLSUM[k] * inv) * eW[k * HH + h];
            g_meanvec[h] = m;
        }
        return;
    }
    __shared__ int sh[SCAN_T];
    const int chunk = (NN + SCAN_T - 1) / SCAN_T;
    int t  = threadIdx.x;
    int lo = t * chunk;
    int hi = min(lo + chunk, NN);
    int sum = 0;
    for (int i = lo; i < hi; i++) sum += G_DEGCNT[i];
    sh[t] = sum;
    __syncthreads();
    for (int off = 1; off < SCAN_T; off <<= 1) {
        int v = (t >= off) ? sh[t - off] : 0;
        __syncthreads();
        sh[t] += v;
        __syncthreads();
    }
    int run = sh[t] - sum;
    for (int i = lo; i < hi; i++) {
        int c = G_DEGCNT[i];
        g_rowptr[i] = run;
        g_wp[i]     = run;
        g_dis[i]    = rsqrtf((float)(c + 1));
        run += c;
    }
    if (t == SCAN_T - 1) g_rowptr[NN] = sh[SCAN_T - 1];
}

// ---------------- CSR fill (scalar — proven form) ----------------
__global__ void csr_fill_edges(const int* __restrict__ ei) {
    int e = blockIdx.x * blockDim.x + threadIdx.x;
    if (e >= EE) return;
    int s = ei[e];
    int d = ei[EE + e];
    int pos = atomicAdd(&g_wp[d], 1);
    g_col[pos] = s;
}

// ---------------- SGEMM (layers 1,2): R4-proven, dis-prescaled epilogue ----------------
__global__ __launch_bounds__(256) void sgemm_kernel(const float* __restrict__ A,
                                                    const float* __restrict__ B,
                                                    __half* __restrict__ C, int M) {
    __shared__ float As[8][128];
    __shared__ float Bs[8][128];
    const int tid  = threadIdx.x;
    const int row0 = blockIdx.x * 128;
    const int ar = tid >> 1, ac = (tid & 1) * 4;
    const int br = tid >> 5, bc = (tid & 31) * 4;
    const int ty = tid >> 4, tx = tid & 15;

    float acc[8][8];
    #pragma unroll
    for (int m = 0; m < 8; m++)
        #pragma unroll
        for (int n = 0; n < 8; n++) acc[m][n] = 0.f;

    for (int k0 = 0; k0 < 128; k0 += 8) {
        int gr = row0 + ar;
        float4 av = (gr < M) ? *(const float4*)&A[(size_t)gr * 128 + k0 + ac]
                             : make_float4(0.f, 0.f, 0.f, 0.f);
        As[ac + 0][ar] = av.x;
        As[ac + 1][ar] = av.y;
        As[ac + 2][ar] = av.z;
        As[ac + 3][ar] = av.w;
        *(float4*)&Bs[br][bc] = *(const float4*)&B[(size_t)(k0 + br) * 128 + bc];
        __syncthreads();
        #pragma unroll
        for (int k = 0; k < 8; k++) {
            float a[8], b[8];
            #pragma unroll
            for (int m = 0; m < 8; m++) a[m] = As[k][ty * 8 + m];
            #pragma unroll
            for (int n = 0; n < 8; n++) b[n] = Bs[k][tx * 8 + n];
            #pragma unroll
            for (int m = 0; m < 8; m++)
                #pragma unroll
                for (int n = 0; n < 8; n++) acc[m][n] = fmaf(a[m], b[n], acc[m][n]);
        }
        __syncthreads();
    }
    #pragma unroll
    for (int m = 0; m < 8; m++) {
        int row = row0 + ty * 8 + m;
        if (row < M) {
            float s = g_dis[row];
            __align__(16) __half2 h[4];
            #pragma unroll
            for (int q = 0; q < 4; q++)
                h[q] = __floats2half2_rn(acc[m][2 * q] * s, acc[m][2 * q + 1] * s);
            *(uint4*)&C[(size_t)row * 128 + tx * 8] = *(const uint4*)h;
        }
    }
}

// ---------------- aggregation: warp/node, fp16 gather (R4-proven form) ----------------
// presc: 1 if table rows are NOT dis-prescaled (layer 0 fused gemm) -> multiply
// gathered row by dis[src] here via g_dis lookup... but that reintroduces the
// per-neighbor scalar load that regressed (R11). Instead: for layer 0 the
// self+neighbor sum needs dis[src]*h[src]; we fold dis[src] by scaling the
// gathered row with g_dis[c]. Only layer 0 pays this (one extra LDG.32/row).
__global__ __launch_bounds__(256) void agg_kernel(const __half* __restrict__ t,
                                                  const float* __restrict__ bias,
                                                  float* __restrict__ out,
                                                  int addmean, int presc) {
    int warp = (blockIdx.x * blockDim.x + threadIdx.x) >> 5;
    int lane = threadIdx.x & 31;
    if (warp >= NN) return;
    int s = g_rowptr[warp];
    int e = g_rowptr[warp + 1];
    float disd = g_dis[warp];

    // self-loop row
    uint2 raw = *(const uint2*)(t + (size_t)warp * 128 + lane * 4);
    float2 p0 = __half22float2(*(const __half2*)&raw.x);
    float2 p1 = __half22float2(*(const __half2*)&raw.y);
    float wself = presc ? disd : 1.f;
    float4 acc  = make_float4(p0.x * wself, p0.y * wself, p1.x * wself, p1.y * wself);
    float4 acc2 = make_float4(0.f, 0.f, 0.f, 0.f);

    int p = s;
    for (; p + 1 < e; p += 2) {
        int c0 = g_col[p];
        int c1 = g_col[p + 1];
        uint2 r0 = *(const uint2*)(t + (size_t)c0 * 128 + lane * 4);
        uint2 r1 = *(const uint2*)(t + (size_t)c1 * 128 + lane * 4);
        float w0 = presc ? g_dis[c0] : 1.f;
        float w1 = presc ? g_dis[c1] : 1.f;
        float2 a0 = __half22float2(*(const __half2*)&r0.x);
        float2 a1 = __half22float2(*(const __half2*)&r0.y);
        float2 b0 = __half22float2(*(const __half2*)&r1.x);
        float2 b1 = __half22float2(*(const __half2*)&r1.y);
        acc.x  = fmaf(a0.x, w0, acc.x);  acc.y  = fmaf(a0.y, w0, acc.y);
        acc.z  = fmaf(a1.x, w0, acc.z);  acc.w  = fmaf(a1.y, w0, acc.w);
        acc2.x = fmaf(b0.x, w1, acc2.x); acc2.y = fmaf(b0.y, w1, acc2.y);
        acc2.z = fmaf(b1.x, w1, acc2.z); acc2.w = fmaf(b1.y, w1, acc2.w);
    }
    if (p < e) {
        int c0 = g_col[p];
        uint2 r0 = *(const uint2*)(t + (size_t)c0 * 128 + lane * 4);
        float w0 = presc ? g_dis[c0] : 1.f;
        float2 a0 = __half22float2(*(const __half2*)&r0.x);
        float2 a1 = __half22float2(*(const __half2*)&r0.y);
        acc.x = fmaf(a0.x, w0, acc.x); acc.y = fmaf(a0.y, w0, acc.y);
        acc.z = fmaf(a1.x, w0, acc.z); acc.w = fmaf(a1.y, w0, acc.w);
    }
    acc.x += acc2.x; acc.y += acc2.y; acc.z += acc2.z; acc.w += acc2.w;

    float4 bb = *(const float4*)(bias + lane * 4);
    acc.x = fmaxf(fmaf(acc.x, disd, bb.x), 0.f);
    acc.y = fmaxf(fmaf(acc.y, disd, bb.y), 0.f);
    acc.z = fmaxf(fmaf(acc.z, disd, bb.z), 0.f);
    acc.w = fmaxf(fmaf(acc.w, disd, bb.w), 0.f);
    if (addmean) {
        float4 mv = *(const float4*)(g_meanvec + lane * 4);
        acc.x += mv.x; acc.y += mv.y; acc.z += mv.z; acc.w += mv.w;
    }
    *(float4*)(out + (size_t)warp * 128 + lane * 4) = acc;
}

// ---------------- fused pooling (max+mean per graph) + MLP ----------------
__global__ __launch_bounds__(128) void pool_mlp_kernel(const float* __restrict__ x,
                                                       const int* __restrict__ batch,
                                                       const float* __restrict__ l1W,
                                                       const float* __restrict__ l1b,
                                                       const float* __restrict__ l2W,
                                                       const float* __restrict__ l2b,
                                                       float* __restrict__ out) {
    int g = blockIdx.x;
    int d = threadIdx.x;
    int lo = 0, hi = NN;
    while (lo < hi) { int mid = (lo + hi) >> 1; if (batch[mid] < g) lo = mid + 1; else hi = mid; }
    int start = lo;
    hi = NN;
    while (lo < hi) { int mid = (lo + hi) >> 1; if (batch[mid] < g + 1) lo = mid + 1; else hi = mid; }
    int end = lo;

    float mx = -3.402823466e38f, sm = 0.f;
    for (int i = start; i < end; i++) {
        float v = x[(size_t)i * 128 + d];
        mx = fmaxf(mx, v);
        sm += v;
    }
    __shared__ float pooled[256];
    __shared__ float hid[64];
    pooled[d]       = mx;
    pooled[128 + d] = sm / (float)(end - start);
    __syncthreads();
    if (d < 64) {
        float h = l1b[d];
        #pragma unroll 8
        for (int k = 0; k < 256; k++) h = fmaf(pooled[k], l1W[k * 64 + d], h);
        hid[d] = fmaxf(h, 0.f);
    }
    __syncthreads();
    if (d == 0) {
        float s = l2b[0];
        #pragma unroll 8
        for (int k = 0; k < 64; k++) s = fmaf(hid[k], l2W[k], s);
        out[g] = s;
    }
}

// ---------------- launch: single stream, block-fused overlap ----------------
extern "C" void kernel_launch(void* const* d_in, const int* in_sizes, int n_in,
                              void* d_out, int out_size) {
    const float* x    = (const float*)d_in[0];
    const int*   ei   = (const int*)  d_in[1];
    const float* ea   = (const float*)d_in[2];
    const int*   bat  = (const int*)  d_in[3];
    const float* W0   = (const float*)d_in[4];
    const float* b0   = (const float*)d_in[5];
    const float* W1   = (const float*)d_in[6];
    const float* b1   = (const float*)d_in[7];
    const float* W2   = (const float*)d_in[8];
    const float* b2   = (const float*)d_in[9];
    const float* eW   = (const float*)d_in[10];
    const float* eb   = (const float*)d_in[11];
    const float* l1W  = (const float*)d_in[12];
    const float* l1b  = (const float*)d_in[13];
    const float* l2W  = (const float*)d_in[14];
    const float* l2b  = (const float*)d_in[15];
    float* out = (float*)d_out;

    __half *t;
    float *x1, *x2;
    int *blob;
    cudaGetSymbolAddress((void**)&t,  g_t);
    cudaGetSymbolAddress((void**)&x1, g_x1);
    cudaGetSymbolAddress((void**)&x2, g_x2);
    cudaGetSymbolAddress((void**)&blob, g_blob);

    const int TB = 256;
    const int agg_grid = (NN * 32 + TB - 1) / TB;

    cudaMemsetAsync(blob, 0, (NN + ED) * sizeof(int));
    // gemm0 (un-prescaled) + degree + colsum, all concurrent in one launch
    fused0_kernel<<<GEMM_GRID + DEG_GRID + COL_GRID, TB>>>(x, W0, t, ei, ea, NN);
    scan_meanvec_kernel<<<2, SCAN_T>>>(eW, eb);
    csr_fill_edges<<<(EE + TB - 1) / TB, TB>>>(ei);
    // layer 0: table not prescaled -> presc=1 (dis[src] applied in-gather)
    agg_kernel<<<agg_grid, TB>>>(t, b0, x1, 0, 1);
    // layers 1,2: prescaled epilogue as proven
    sgemm_kernel<<<GEMM_GRID, TB>>>(x1, W1, t, NN);
    agg_kernel<<<agg_grid, TB>>>(t, b1, x2, 0, 0);
    sgemm_kernel<<<GEMM_GRID, TB>>>(x2, W2, t, NN);
    agg_kernel<<<agg_grid, TB>>>(t, b2, x1, 1, 0);
    pool_mlp_kernel<<<GG, HH>>>(x1, bat, l1W, l1b, l2W, l2b, out);
}